// round 1
// baseline (speedup 1.0000x reference)
#include <cuda_runtime.h>

// ---------------------------------------------------------------------------
// Inverse DTCWT qshift level, fully fused.
//
// Filter algebra (derived from reference):
//   h0a = {A0, 0, A2', A3, A4, A5, 0, A7', 0, 0}   (primed = negative values)
//   Upsampling filter F0 (ha=h0a, hb=reverse(h0a), sum>0 branch):
//     out[4i+s] = sum_{j} T0[s][j] * X[reflect(2i + O0[s][j])]
//   F1 (ha=h1a, hb=h1b, sum<0 branch) is a phase/sign permutation of F0.
//   Only 3 taps are nonzero for every phase s.
// ---------------------------------------------------------------------------

static constexpr float A0 =  0.0351638365171441f;
static constexpr float A2 = -0.0883294244510729f;
static constexpr float A3c = 0.233890320607236f;
static constexpr float A4 =  0.760272369066126f;
static constexpr float A5 =  0.587518297723561f;
static constexpr float A7 = -0.114301837144249f;
static constexpr float RS2 = 0.70710678118654752440f; // 1/sqrt(2)

// [filter 0/1][phase s][tap]
__constant__ int c_off[2][4][3] = {
    { { 4, 2, 0 }, { 3, 1, -1 }, { 2, 0, -2 }, { 1, -1, -3 } },
    { { 3, 1, -1 }, { 4, 2, 0 }, { 1, -1, -3 }, { 2, 0, -2 } }
};
__constant__ float c_tap[2][4][3] = {
    { { A0, A2, A4 }, { A7, A5, A3c }, { A3c, A5, A7 }, { A4, A2, A0 } },
    { { A7, A5, A3c }, { -A0, -A2, -A4 }, { -A4, -A2, -A0 }, { A3c, A5, A7 } }
};

// reflect index into [0,127] for x in [-5, 132]
__device__ __forceinline__ int rf128(int x) {
    return x < 0 ? (-1 - x) : (x > 127 ? (255 - x) : x);
}

// Input geometry (fixed for this problem)
#define IH   128      // input image height (Yl)
#define IW   128      // input image width
#define HH2  64       // Yh spatial dims
#define OW   256      // output width
#define OH   256      // output height
#define WIN  40       // y-row window per 64-output-row strip
#define NTHREADS 256

__global__ __launch_bounds__(NTHREADS, 2)
void dtcwt_inv_kernel(const float* __restrict__ Yl,
                      const float* __restrict__ Yhr,
                      const float* __restrict__ Yhi,
                      float* __restrict__ out)
{
    extern __shared__ float sm[];
    float* y1s  = sm;                 // WIN * 256
    float* y2s  = sm + WIN * OW;      // WIN * 256
    float* yl_s = sm + 2 * WIN * OW;  // 128
    float* lh_s = yl_s + 128;         // 128
    float* hl_s = yl_s + 256;         // 128
    float* hh_s = yl_s + 384;         // 128

    const int tid = threadIdx.x;
    const int S   = blockIdx.x;   // strip: output rows [S*64, S*64+63]
    const int g   = blockIdx.y;   // image index (b*C + c)

    const float* ylg  = Yl  + (size_t)g * (IH * IW);
    const float* yhrg = Yhr + (size_t)g * (6 * HH2 * HH2);
    const float* yhig = Yhi + (size_t)g * (6 * HH2 * HH2);
    float*       og   = out + (size_t)g * (OH * OW);

    const int i0 = S * 16;
    const int ws = 2 * i0 - 4;    // unreflected y-row index of window slot 0

    // ---- per-thread horizontal filter parameters (phase s fixed per thread)
    const int s   = tid & 3;
    const int ic2 = (tid >> 2) << 1;   // 2 * (output col / 4)
    const int x00 = rf128(ic2 + c_off[0][s][0]);
    const int x01 = rf128(ic2 + c_off[0][s][1]);
    const int x02 = rf128(ic2 + c_off[0][s][2]);
    const int x10 = rf128(ic2 + c_off[1][s][0]);
    const int x11 = rf128(ic2 + c_off[1][s][1]);
    const int x12 = rf128(ic2 + c_off[1][s][2]);
    const float t00 = c_tap[0][s][0], t01 = c_tap[0][s][1], t02 = c_tap[0][s][2];
    const float t10 = c_tap[1][s][0], t11 = c_tap[1][s][1], t12 = c_tap[1][s][2];

    // ---- staging role split (warp-uniform: sel constant within each warp pair)
    const int sel = tid >> 6;        // 0: lh(c0,c5)  1: hl(c2,c3)  2: hh(c1,c4)  3: Yl
    const int w   = tid & 63;
    const int c1  = (sel == 1) ? 2 : (sel == 2) ? 1 : 0;
    const int c2  = (sel == 1) ? 3 : (sel == 2) ? 4 : 5;
    float* dst = (sel == 0) ? lh_s : (sel == 1) ? hl_s : hh_s;

    // =========================================================
    // Phase 1: build 40-row window of y1, y2 (horizontal filters)
    // =========================================================
    for (int k = 0; k < WIN; ++k) {
        const int v  = ws + k;
        const int yr = rf128(v);

        if (sel == 3) {
            yl_s[w]      = ylg[yr * IW + w];
            yl_s[w + 64] = ylg[yr * IW + 64 + w];
        } else {
            const int h    = yr >> 1;
            const int base = h * HH2 + w;
            const float w1r = yhrg[c1 * (HH2 * HH2) + base];
            const float w2r = yhrg[c2 * (HH2 * HH2) + base];
            const float w1i = yhig[c1 * (HH2 * HH2) + base];
            const float w2i = yhig[c2 * (HH2 * HH2) + base];
            float e, o;
            if ((yr & 1) == 0) { e = w1r + w2r; o = w1i + w2i; }   // c2q top row
            else               { e = w1i - w2i; o = w2r - w1r; }   // c2q bottom row
            ((float2*)dst)[w] = make_float2(e * RS2, o * RS2);
        }
        __syncthreads();

        // y1 = F0(Yl row) + F1(hl row);  y2 = F0(lh row) + F1(hh row)
        float y1 = t00 * yl_s[x00] + t01 * yl_s[x01] + t02 * yl_s[x02]
                 + t10 * hl_s[x10] + t11 * hl_s[x11] + t12 * hl_s[x12];
        float y2 = t00 * lh_s[x00] + t01 * lh_s[x01] + t02 * lh_s[x02]
                 + t10 * hh_s[x10] + t11 * hh_s[x11] + t12 * hh_s[x12];
        y1s[k * OW + tid] = y1;
        y2s[k * OW + tid] = y2;
        __syncthreads();
    }

    // =========================================================
    // Phase 2: vertical filters out = F0(y1) + F1(y2)
    // output row 4i+s; window slot kb = 2*(i - i0) + 4
    // =========================================================
    const int orow0 = S * 64;
#pragma unroll
    for (int ii = 0; ii < 16; ++ii) {
        const int kb = 2 * ii + 4;
        const float* Y1 = y1s + kb * OW + tid;
        const float* Y2 = y2s + kb * OW + tid;

        const float v0 = A0  * Y1[4 * OW] + A2  * Y1[2 * OW] + A4 * Y1[0]
                       + A7  * Y2[3 * OW] + A5  * Y2[1 * OW] + A3c * Y2[-1 * OW];
        const float v1 = A7  * Y1[3 * OW] + A5  * Y1[1 * OW] + A3c * Y1[-1 * OW]
                       - A0  * Y2[4 * OW] - A2  * Y2[2 * OW] - A4 * Y2[0];
        const float v2 = A3c * Y1[2 * OW] + A5  * Y1[0]      + A7 * Y1[-2 * OW]
                       - A4  * Y2[1 * OW] - A2  * Y2[-1 * OW] - A0 * Y2[-3 * OW];
        const float v3 = A4  * Y1[1 * OW] + A2  * Y1[-1 * OW] + A0 * Y1[-3 * OW]
                       + A3c * Y2[2 * OW] + A5  * Y2[0]      + A7 * Y2[-2 * OW];

        const int r = orow0 + 4 * ii;
        og[(r + 0) * OW + tid] = v0;
        og[(r + 1) * OW + tid] = v1;
        og[(r + 2) * OW + tid] = v2;
        og[(r + 3) * OW + tid] = v3;
    }
}

extern "C" void kernel_launch(void* const* d_in, const int* in_sizes, int n_in,
                              void* d_out, int out_size)
{
    const float* Yl  = (const float*)d_in[0];
    const float* Yhr = (const float*)d_in[1];
    const float* Yhi = (const float*)d_in[2];
    float* out = (float*)d_out;

    const int n_img = in_sizes[0] / (IH * IW);   // 512 for (8,64,128,128)
    const size_t smem = (size_t)(2 * WIN * OW + 4 * 128) * sizeof(float); // 83968 B

    cudaFuncSetAttribute(dtcwt_inv_kernel,
                         cudaFuncAttributeMaxDynamicSharedMemorySize, (int)smem);

    dim3 grid(4, n_img);
    dtcwt_inv_kernel<<<grid, NTHREADS, smem>>>(Yl, Yhr, Yhi, out);
}

// round 2
// speedup vs baseline: 2.3381x; 2.3381x over previous
#include <cuda_runtime.h>

// ---------------------------------------------------------------------------
// Inverse DTCWT qshift level, fully fused, barrier-free.
//
// Filter algebra (derived from reference, validated in R1 @ rel_err 9.4e-8):
//   The 10-tap qshift synthesis filters reduce, per output phase s = n & 3,
//   to 3 nonzero taps over input samples at reflect(2*(n>>2) + off).
//   F1 (high-pass pair) is a phase/sign permutation of F0 (low-pass pair).
//
// R2 design: each warp owns 32 output columns x 64 output rows.
//   - per y-row, lane l loads input column reflect(16*warp - 3 + l) of each
//     of the 4 intermediate arrays (Yl row, and c2q rows lh/hl/hh computed
//     inline from Yhr/Yhi); horizontal taps gathered via __shfl_sync with
//     per-lane constant source lanes (range [0,21], always in-warp).
//   - vertical filter streams an 8-row register window (rows 2i-3..2i+4),
//     emits 4 output rows per step, shifts by 2.
//   No shared memory, no __syncthreads.
// ---------------------------------------------------------------------------

static constexpr float A0 =  0.0351638365171441f;
static constexpr float A2 = -0.0883294244510729f;
static constexpr float A3c = 0.233890320607236f;
static constexpr float A4 =  0.760272369066126f;
static constexpr float A5 =  0.587518297723561f;
static constexpr float A7 = -0.114301837144249f;
static constexpr float RS2 = 0.70710678118654752440f; // 1/sqrt(2)

// [filter 0/1][phase s][tap]
__constant__ int c_off[2][4][3] = {
    { { 4, 2, 0 }, { 3, 1, -1 }, { 2, 0, -2 }, { 1, -1, -3 } },
    { { 3, 1, -1 }, { 4, 2, 0 }, { 1, -1, -3 }, { 2, 0, -2 } }
};
__constant__ float c_tap[2][4][3] = {
    { { A0, A2, A4 }, { A7, A5, A3c }, { A3c, A5, A7 }, { A4, A2, A0 } },
    { { A7, A5, A3c }, { -A0, -A2, -A4 }, { -A4, -A2, -A0 }, { A3c, A5, A7 } }
};

// reflect index into [0,127] for x in [-5, 250]
__device__ __forceinline__ int rf128(int x) {
    return x < 0 ? (-1 - x) : (x > 127 ? (255 - x) : x);
}

#define IH   128
#define IW   128
#define HH2  64
#define OW   256
#define NTHREADS 256

__global__ __launch_bounds__(NTHREADS, 4)
void dtcwt_inv_kernel(const float* __restrict__ Yl,
                      const float* __restrict__ Yhr,
                      const float* __restrict__ Yhi,
                      float* __restrict__ out)
{
    const int tid  = threadIdx.x;
    const int warp = tid >> 5;
    const int lane = tid & 31;
    const int S    = blockIdx.x;   // strip: output rows [S*64, S*64+63]
    const int g    = blockIdx.y;   // image index (b*C + c)

    const float* ylg  = Yl  + (size_t)g * (IH * IW);
    const float* yhrg = Yhr + (size_t)g * (6 * HH2 * HH2);
    const float* yhig = Yhi + (size_t)g * (6 * HH2 * HH2);
    float*       og   = out + (size_t)g * (OW * OW);

    // ---- per-lane constants -------------------------------------------------
    const int col = warp * 32 + lane;     // output column
    const int s   = col & 3;              // horizontal phase

    const float t00 = c_tap[0][s][0], t01 = c_tap[0][s][1], t02 = c_tap[0][s][2];
    const float t10 = c_tap[1][s][0], t11 = c_tap[1][s][1], t12 = c_tap[1][s][2];

    // shfl source lanes: srclane = (ic2 + off) - (16*warp - 3), ic2 = 16w + 2*(lane>>2)
    const int lb  = (lane >> 2) << 1;
    const int s00 = lb + c_off[0][s][0] + 3;
    const int s01 = lb + c_off[0][s][1] + 3;
    const int s02 = lb + c_off[0][s][2] + 3;
    const int s10 = lb + c_off[1][s][0] + 3;
    const int s11 = lb + c_off[1][s][1] + 3;
    const int s12 = lb + c_off[1][s][2] + 3;

    // this lane's staged input column (reflected), valid for all lanes
    const int x   = rf128(16 * warp - 3 + lane);
    const int p   = x & 1;                // c2q column parity
    const int wcp = x >> 1;               // Yh column

    // ---- per-row compute: y1, y2 at this lane's column for absolute y-row v
    auto crow = [&](int v, float& o1, float& o2) {
        const int yr   = rf128(v);
        const int h    = yr >> 1;
        const int q    = yr & 1;          // c2q row parity
        const int hoff = h * HH2 + wcp;

        const float ylv = ylg[yr * IW + x];

        // c2q element: base array and signs from (p, q)
        const float* bp = ((p ^ q) ? yhig : yhrg) + hoff;
        const float a_lh1 = bp[0 * 4096], a_lh2 = bp[5 * 4096];
        const float a_hl1 = bp[2 * 4096], a_hl2 = bp[3 * 4096];
        const float a_hh1 = bp[1 * 4096], a_hh2 = bp[4 * 4096];

        const float sg1 = (q & p)       ? -RS2 : RS2;
        const float sg2 = (q & (p ^ 1)) ? -RS2 : RS2;

        const float lhv = sg1 * a_lh1 + sg2 * a_lh2;
        const float hlv = sg1 * a_hl1 + sg2 * a_hl2;
        const float hhv = sg1 * a_hh1 + sg2 * a_hh2;

        o1 = t00 * __shfl_sync(0xffffffffu, ylv, s00)
           + t01 * __shfl_sync(0xffffffffu, ylv, s01)
           + t02 * __shfl_sync(0xffffffffu, ylv, s02)
           + t10 * __shfl_sync(0xffffffffu, hlv, s10)
           + t11 * __shfl_sync(0xffffffffu, hlv, s11)
           + t12 * __shfl_sync(0xffffffffu, hlv, s12);
        o2 = t00 * __shfl_sync(0xffffffffu, lhv, s00)
           + t01 * __shfl_sync(0xffffffffu, lhv, s01)
           + t02 * __shfl_sync(0xffffffffu, lhv, s02)
           + t10 * __shfl_sync(0xffffffffu, hhv, s10)
           + t11 * __shfl_sync(0xffffffffu, hhv, s11)
           + t12 * __shfl_sync(0xffffffffu, hhv, s12);
    };

    // ---- vertical streaming window: w?[j] = y row (2i - 3 + j), j = 0..7 ----
    const int i0 = S * 16;
    float w1[8], w2[8];
#pragma unroll
    for (int j = 0; j < 8; ++j)
        crow(2 * i0 - 3 + j, w1[j], w2[j]);

    int r = S * 64;
#pragma unroll 2
    for (int ii = 0; ii < 16; ++ii) {
        // emit 4 output rows at this lane's column
        const float v0 = A0  * w1[7] + A2  * w1[5] + A4 * w1[3]
                       + A7  * w2[6] + A5  * w2[4] + A3c * w2[2];
        const float v1 = A7  * w1[6] + A5  * w1[4] + A3c * w1[2]
                       - A0  * w2[7] - A2  * w2[5] - A4 * w2[3];
        const float v2 = A3c * w1[5] + A5  * w1[3] + A7 * w1[1]
                       - A4  * w2[4] - A2  * w2[2] - A0 * w2[0];
        const float v3 = A4  * w1[4] + A2  * w1[2] + A0 * w1[0]
                       + A3c * w2[5] + A5  * w2[3] + A7 * w2[1];

        og[(r + 0) * OW + col] = v0;
        og[(r + 1) * OW + col] = v1;
        og[(r + 2) * OW + col] = v2;
        og[(r + 3) * OW + col] = v3;
        r += 4;

        if (ii < 15) {
#pragma unroll
            for (int j = 0; j < 6; ++j) { w1[j] = w1[j + 2]; w2[j] = w2[j + 2]; }
            const int i = i0 + ii;
            crow(2 * i + 5, w1[6], w2[6]);
            crow(2 * i + 6, w1[7], w2[7]);
        }
    }
}

extern "C" void kernel_launch(void* const* d_in, const int* in_sizes, int n_in,
                              void* d_out, int out_size)
{
    const float* Yl  = (const float*)d_in[0];
    const float* Yhr = (const float*)d_in[1];
    const float* Yhi = (const float*)d_in[2];
    float* out = (float*)d_out;

    const int n_img = in_sizes[0] / (IH * IW);   // 512 for (8,64,128,128)

    dim3 grid(4, n_img);
    dtcwt_inv_kernel<<<grid, NTHREADS>>>(Yl, Yhr, Yhi, out);
}